// round 8
// baseline (speedup 1.0000x reference)
#include <cuda_runtime.h>
#include <cuda_bf16.h>
#include <cstdint>

// Gather: out[g][row][j*32+k] = in[row][g*512 + j*64 + k]
//   out flat float4 idx i: g=i>>20, row=(i>>6)&16383, v=i&63
//   src (float4 units) = row*1024 + g*128 + (v>>3)*16 + (v&7)
//
// DIRTY-WRITE L2 RESIDENCY SCHEME (last untested traffic-reduction class):
//   The output (128 MiB) is rewritten at identical addresses every graph
//   replay, and L2 is 126 MB. A dirty L2 line rewritten in place before
//   eviction generates NO DRAM writeback. So:
//     * groups 0..6 (112 MiB, strictly sub-capacity): default stores
//       (write-allocate, evict-normal) -> stays dirty-resident across
//       replays -> steady-state write traffic ~0 for this subset.
//     * group 7 (16 MiB): __stcs (evict-first) -> streamed, protects the
//       pinned set.
//     * ALL reads: __ldcs (evict-first allocate) -> read stream cannot
//       displace the pinned dirty set.
//   Ideal steady-state DRAM traffic: 128 MiB reads + ~16 MiB writes
//   (vs 256 MiB now) -> bench ~28-35us. If the L2 replacement policy
//   ignores eviction classes across replays, exactly neutral (~45.4us).

__global__ void __launch_bounds__(512)
fuse_slice_cat_kernel(const float4* __restrict__ in, float4* __restrict__ out)
{
    unsigned int b   = blockIdx.x;
    unsigned int g   = b & 7u;          // group fastest across blocks
    unsigned int t   = b >> 3;          // 64-row tile
    unsigned int tid = threadIdx.x;

    unsigned int i0  = (g << 20) + (t << 12) + tid;
    unsigned int row = (t << 6) + (tid >> 6);   // +8 rows per k-step
    unsigned int v   = tid & 63u;
    unsigned int src = row * 1024u + g * 128u + (v >> 3) * 16u + (v & 7u);

    float4 r[8];
    #pragma unroll
    for (int k = 0; k < 8; ++k)
        r[k] = __ldcs(&in[src + (unsigned)k * 8192u]);  // evict-first reads

    if (g < 7u) {
        // Pinned output subset: default (evict-normal) write-allocate stores.
        #pragma unroll
        for (int k = 0; k < 8; ++k)
            out[i0 + (unsigned)k * 512u] = r[k];
    } else {
        // Streamed output subset: evict-first.
        #pragma unroll
        for (int k = 0; k < 8; ++k)
            __stcs(&out[i0 + (unsigned)k * 512u], r[k]);
    }
}

extern "C" void kernel_launch(void* const* d_in, const int* in_sizes, int n_in,
                              void* d_out, int out_size)
{
    const float4* in  = (const float4*)d_in[0];
    float4*       out = (float4*)d_out;

    // 2^23 float4 total; 4096 per block -> 2048 blocks (256 row-tiles x 8 groups).
    fuse_slice_cat_kernel<<<2048, 512>>>(in, out);
}

// round 9
// speedup vs baseline: 1.0229x; 1.0229x over previous
#include <cuda_runtime.h>
#include <cuda_bf16.h>
#include <cstdint>

// Gather: out[g][row][j*32+k] = in[row][g*512 + j*64 + k]
//   g in [0,8), j in [0,8), k in [0,32), row in [0,16384)
// Output is the 8 group tensors concatenated flat:
//   out flat idx = g*(16384*256) + row*256 + j*32 + k
// All dims are powers of two -> pure shift/mask indexing.
// Work unit: one float4 (16B). Total float4s = 16384*2048/4 = 2^23.
//
// TERMINAL KERNEL (best of 8 structurally distinct designs, R1 = 45.088us):
// steady state is pinned at ~5.9 TB/s for the irreducible 256 MiB/replay
// traffic (half-dense reads + dense writes). Falsified levers: deeper MLP
// (to 32 lines/thread), 256-bit accesses, every L2 eviction-class scheme
// (clean-read pin, no-allocate, dirty-write pin), concurrency remaps, and
// block-granularity tuning — all within +-1.5% of this kernel.

__global__ void __launch_bounds__(256)
fuse_slice_cat_kernel(const float4* __restrict__ in, float4* __restrict__ out)
{
    unsigned int i = blockIdx.x * 256u + threadIdx.x;   // base float4 index
    const unsigned int stride = gridDim.x * 256u;       // = 2^21 with grid 8192

    #pragma unroll
    for (int it = 0; it < 4; ++it) {
        // i in [0, 2^23)
        unsigned int g   = i >> 20;          // group (0..7)
        unsigned int row = (i >> 6) & 16383; // row; 64 float4 per output row
        unsigned int v   = i & 63;           // float4 within the 256-col output row
        unsigned int j   = v >> 3;           // slice index (0..7)
        unsigned int kq  = v & 7;            // float4 within slice

        // input row stride = 4096 floats = 1024 float4
        // input col (float4 units) = g*128 + j*16 + kq
        unsigned int src = row * 1024u + g * 128u + j * 16u + kq;

        out[i] = in[src];
        i += stride;
    }
}

extern "C" void kernel_launch(void* const* d_in, const int* in_sizes, int n_in,
                              void* d_out, int out_size)
{
    const float4* in  = (const float4*)d_in[0];
    float4*       out = (float4*)d_out;

    // 2^23 float4s total; 4 per thread -> 2^21 threads -> 8192 blocks of 256.
    fuse_slice_cat_kernel<<<8192, 256>>>(in, out);
}

// round 10
// speedup vs baseline: 1.0384x; 1.0152x over previous
#include <cuda_runtime.h>
#include <cuda_bf16.h>
#include <cstdint>

// Gather: out[g][row][j*32+k] = in[row][g*512 + j*64 + k]
//   out flat float4 idx i: g=i>>20, row=(i>>6)&16383, v=i&63
//   src (float4 units) = row*1024 + g*128 + (v>>3)*16 + (v&7)
//
// R1 structure (best measured: 44.8us) with two micro-changes:
//   * all 4 loads front-batched before any store (MLP=4/thread at ~32 regs,
//     preserving R1's ~78% occupancy — the untested point between R1's
//     serialized MLP~1 and R2's reg-heavy MLP=8),
//   * compile-time-constant grid stride (2^21) — removes gridDim S2R and
//     one IMAD per iteration.
// Traffic is pinned at 256 MiB/replay @ ~5.9 TB/s; target is the lower
// edge of the measured 44.8-45.8us band.

#define GRID_BLOCKS 8192u
#define STRIDE      (GRID_BLOCKS * 256u)   // 2^21 float4s

__global__ void __launch_bounds__(256)
fuse_slice_cat_kernel(const float4* __restrict__ in, float4* __restrict__ out)
{
    const unsigned int i0 = blockIdx.x * 256u + threadIdx.x;

    unsigned int idx[4];
    unsigned int srcI[4];

    #pragma unroll
    for (int it = 0; it < 4; ++it) {
        unsigned int i   = i0 + (unsigned)it * STRIDE;
        unsigned int g   = i >> 20;
        unsigned int row = (i >> 6) & 16383u;
        unsigned int v   = i & 63u;
        idx[it]  = i;
        srcI[it] = row * 1024u + g * 128u + (v >> 3) * 16u + (v & 7u);
    }

    float4 r[4];
    #pragma unroll
    for (int it = 0; it < 4; ++it)      // 4 loads in flight before any store
        r[it] = in[srcI[it]];

    #pragma unroll
    for (int it = 0; it < 4; ++it)
        out[idx[it]] = r[it];
}

extern "C" void kernel_launch(void* const* d_in, const int* in_sizes, int n_in,
                              void* d_out, int out_size)
{
    const float4* in  = (const float4*)d_in[0];
    float4*       out = (float4*)d_out;

    fuse_slice_cat_kernel<<<GRID_BLOCKS, 256>>>(in, out);
}